// round 1
// baseline (speedup 1.0000x reference)
#include <cuda_runtime.h>

#define B_ 4
#define S_ 2048
#define E_ 1024
#define H_ 128
#define M_ (B_*S_)

#define SCALE_ 11.31370849898476f   // sqrt(128)

// Scratch for projections (device globals: no allocation allowed)
__device__ float g_q[M_*H_];
__device__ float g_k[M_*H_];
__device__ float g_v[M_*H_];

// ---------------------------------------------------------------------------
// Projection GEMM: out[m][h] = sum_e x[m][e] * W[h][e]
// BM=64, BN=128, BK=16, 128 threads, 8x8 per thread.
// q is pre-scaled by sqrt(H) so the attention kernel skips the multiply.
// ---------------------------------------------------------------------------
#define PBM 64
#define PBN 128
#define PBK 16

__global__ __launch_bounds__(128) void proj_kernel(
    const float* __restrict__ x,
    const float* __restrict__ Wq,
    const float* __restrict__ Wk,
    const float* __restrict__ Wv)
{
    const float* W;
    float* out;
    float oscale;
    if (blockIdx.y == 0)      { W = Wq; out = g_q; oscale = SCALE_; }
    else if (blockIdx.y == 1) { W = Wk; out = g_k; oscale = 1.0f; }
    else                      { W = Wv; out = g_v; oscale = 1.0f; }

    __shared__ float As[PBK][PBM];   // k-major
    __shared__ float Bs[PBK][PBN];   // k-major

    const int tid = threadIdx.x;
    const int ty = tid >> 4;     // 0..7  (8 rows each)
    const int tx = tid & 15;     // 0..15 (8 cols each)
    const int m0 = blockIdx.x * PBM;

    float acc[8][8];
#pragma unroll
    for (int i = 0; i < 8; i++)
#pragma unroll
        for (int j = 0; j < 8; j++) acc[i][j] = 0.0f;

    for (int k0 = 0; k0 < E_; k0 += PBK) {
        // load x tile 64x16 (2 float4 per thread), transpose into As
#pragma unroll
        for (int i = 0; i < 2; i++) {
            int f4 = tid + 128 * i;           // 0..255
            int row = f4 >> 2, c4 = f4 & 3;
            float4 v = *(const float4*)&x[(size_t)(m0 + row) * E_ + k0 + c4 * 4];
            As[c4*4+0][row] = v.x;
            As[c4*4+1][row] = v.y;
            As[c4*4+2][row] = v.z;
            As[c4*4+3][row] = v.w;
        }
        // load W tile 128x16 (4 float4 per thread), transpose into Bs
#pragma unroll
        for (int i = 0; i < 4; i++) {
            int f4 = tid + 128 * i;           // 0..511
            int col = f4 >> 2, c4 = f4 & 3;
            float4 v = *(const float4*)&W[(size_t)col * E_ + k0 + c4 * 4];
            Bs[c4*4+0][col] = v.x;
            Bs[c4*4+1][col] = v.y;
            Bs[c4*4+2][col] = v.z;
            Bs[c4*4+3][col] = v.w;
        }
        __syncthreads();

#pragma unroll
        for (int kk = 0; kk < PBK; kk++) {
            float a[8], b[8];
            *(float4*)&a[0] = *(const float4*)&As[kk][ty*8];
            *(float4*)&a[4] = *(const float4*)&As[kk][ty*8+4];
            *(float4*)&b[0] = *(const float4*)&Bs[kk][tx*8];
            *(float4*)&b[4] = *(const float4*)&Bs[kk][tx*8+4];
#pragma unroll
            for (int i = 0; i < 8; i++)
#pragma unroll
                for (int j = 0; j < 8; j++)
                    acc[i][j] = fmaf(a[i], b[j], acc[i][j]);
        }
        __syncthreads();
    }

#pragma unroll
    for (int i = 0; i < 8; i++) {
        size_t rbase = (size_t)(m0 + ty*8 + i) * H_ + tx*8;
        float4 r0, r1;
        r0.x = acc[i][0]*oscale; r0.y = acc[i][1]*oscale;
        r0.z = acc[i][2]*oscale; r0.w = acc[i][3]*oscale;
        r1.x = acc[i][4]*oscale; r1.y = acc[i][5]*oscale;
        r1.z = acc[i][6]*oscale; r1.w = acc[i][7]*oscale;
        *(float4*)&out[rbase]     = r0;
        *(float4*)&out[rbase + 4] = r1;
    }
}

// ---------------------------------------------------------------------------
// Flash attention (fp32, warp-owns-rows). Q-tile 32, K/V-tile 64.
// Warp w owns q-rows w*4..w*4+3. Scores, softmax stats, and AV accumulators
// all stay in registers; p broadcast to AV via shfl. K and V share one 32KB
// smem buffer (phase split), total static smem exactly 48KB.
// ---------------------------------------------------------------------------
#define QT 32
#define KT 64

__global__ __launch_bounds__(256) void attn_kernel(float* __restrict__ out)
{
    __shared__ float Qs[QT * H_];   // 16KB  Qs[row*128 + h]
    __shared__ float KV[KT * H_];   // 32KB  K phase: [h*64 + c]; V phase: [c*128 + h]

    const int tid  = threadIdx.x;
    const int w    = tid >> 5;      // warp 0..7
    const int lane = tid & 31;

    const int bx = blockIdx.x;          // 0..255, longest-first
    const int b  = bx & 3;
    const int qt = 63 - (bx >> 2);      // q-tile index 0..63
    const int qbase = qt * QT;
    const int base  = b * S_;

    const float* gq = g_q + (size_t)base * H_;
    const float* gk = g_k + (size_t)base * H_;
    const float* gv = g_v + (size_t)base * H_;

    // load Q tile (pre-scaled by sqrt(H) already)
#pragma unroll
    for (int i = 0; i < 4; i++) {
        int f4 = tid + 256 * i;             // 0..1023
        int row = f4 >> 5, h4 = f4 & 31;
        *(float4*)&Qs[row * H_ + h4 * 4] =
            *(const float4*)&gq[(size_t)(qbase + row) * H_ + h4 * 4];
    }

    float4 o[4];
    float  m[4], l[4];
#pragma unroll
    for (int i = 0; i < 4; i++) {
        o[i] = make_float4(0.f, 0.f, 0.f, 0.f);
        m[i] = -1e30f;
        l[i] = 0.f;
    }

    const int r0  = w * 4;
    const int nkt = (qt >> 1) + 1;          // k-tiles needed for causal coverage

    for (int kt = 0; kt < nkt; kt++) {
        const int kb = kt * KT;

        __syncthreads();   // previous AV reads done / Q loads done (kt==0)
        // --- load K tile transposed: KV[h*64 + c] = k[kb+c][h] ---
#pragma unroll
        for (int i = 0; i < 8; i++) {
            int f4 = tid + 256 * i;         // 0..2047
            int c = f4 >> 5, h4 = f4 & 31;
            float4 v = *(const float4*)&gk[(size_t)(kb + c) * H_ + h4 * 4];
            KV[(h4*4+0)*KT + c] = v.x;
            KV[(h4*4+1)*KT + c] = v.y;
            KV[(h4*4+2)*KT + c] = v.z;
            KV[(h4*4+3)*KT + c] = v.w;
        }
        __syncthreads();

        // --- QK^T: s[i][j], rows r0..r0+3, cols lane*2, lane*2+1 ---
        float s[4][2];
#pragma unroll
        for (int i = 0; i < 4; i++) { s[i][0] = 0.f; s[i][1] = 0.f; }

#pragma unroll 4
        for (int h4 = 0; h4 < 32; h4++) {
            float4 qv[4];
#pragma unroll
            for (int i = 0; i < 4; i++)
                qv[i] = *(const float4*)&Qs[(r0 + i) * H_ + h4 * 4];
#pragma unroll
            for (int u = 0; u < 4; u++) {
                float2 kv = *(const float2*)&KV[(h4*4 + u) * KT + lane * 2];
#pragma unroll
                for (int i = 0; i < 4; i++) {
                    float qc = ((const float*)&qv[i])[u];
                    s[i][0] = fmaf(qc, kv.x, s[i][0]);
                    s[i][1] = fmaf(qc, kv.y, s[i][1]);
                }
            }
        }

        // --- causal mask (scale already folded into q) ---
#pragma unroll
        for (int i = 0; i < 4; i++) {
            int qg = qbase + r0 + i;
#pragma unroll
            for (int j = 0; j < 2; j++) {
                int kg = kb + lane * 2 + j;
                if (kg > qg) s[i][j] = -1e30f;
            }
        }

        // --- online softmax (warp-local per row) ---
        float p[4][2];
#pragma unroll
        for (int i = 0; i < 4; i++) {
            float mx = fmaxf(s[i][0], s[i][1]);
            mx = fmaxf(mx, __shfl_xor_sync(0xffffffffu, mx, 16));
            mx = fmaxf(mx, __shfl_xor_sync(0xffffffffu, mx, 8));
            mx = fmaxf(mx, __shfl_xor_sync(0xffffffffu, mx, 4));
            mx = fmaxf(mx, __shfl_xor_sync(0xffffffffu, mx, 2));
            mx = fmaxf(mx, __shfl_xor_sync(0xffffffffu, mx, 1));
            float mn   = fmaxf(m[i], mx);
            float corr = __expf(m[i] - mn);
            p[i][0] = __expf(s[i][0] - mn);
            p[i][1] = __expf(s[i][1] - mn);
            float rs = p[i][0] + p[i][1];
            rs += __shfl_xor_sync(0xffffffffu, rs, 16);
            rs += __shfl_xor_sync(0xffffffffu, rs, 8);
            rs += __shfl_xor_sync(0xffffffffu, rs, 4);
            rs += __shfl_xor_sync(0xffffffffu, rs, 2);
            rs += __shfl_xor_sync(0xffffffffu, rs, 1);
            l[i] = l[i] * corr + rs;
            m[i] = mn;
            o[i].x *= corr; o[i].y *= corr; o[i].z *= corr; o[i].w *= corr;
        }

        __syncthreads();   // QK reads of KV done
        // --- load V tile: KV[c*128 + h] ---
#pragma unroll
        for (int i = 0; i < 8; i++) {
            int f4 = tid + 256 * i;
            int c = f4 >> 5, h4 = f4 & 31;
            *(float4*)&KV[c * H_ + h4 * 4] =
                *(const float4*)&gv[(size_t)(kb + c) * H_ + h4 * 4];
        }
        __syncthreads();

        // --- AV: o[i] (cols lane*4..+3) += p[i][kk] * v[kk] ---
#pragma unroll 4
        for (int kk = 0; kk < KT; kk++) {
            float4 vv = *(const float4*)&KV[kk * H_ + lane * 4];
            int src = kk >> 1;
            int j   = kk & 1;
#pragma unroll
            for (int i = 0; i < 4; i++) {
                float pr = __shfl_sync(0xffffffffu, p[i][j], src);
                o[i].x = fmaf(pr, vv.x, o[i].x);
                o[i].y = fmaf(pr, vv.y, o[i].y);
                o[i].z = fmaf(pr, vv.z, o[i].z);
                o[i].w = fmaf(pr, vv.w, o[i].w);
            }
        }
    }

    // --- epilogue: normalize and store ---
#pragma unroll
    for (int i = 0; i < 4; i++) {
        float inv = 1.0f / l[i];
        float4 r;
        r.x = o[i].x * inv; r.y = o[i].y * inv;
        r.z = o[i].z * inv; r.w = o[i].w * inv;
        *(float4*)&out[(size_t)(base + qbase + r0 + i) * H_ + lane * 4] = r;
    }
}

// ---------------------------------------------------------------------------
extern "C" void kernel_launch(void* const* d_in, const int* in_sizes, int n_in,
                              void* d_out, int out_size)
{
    const float* x  = (const float*)d_in[0];
    const float* Wq = (const float*)d_in[1];
    const float* Wk = (const float*)d_in[2];
    const float* Wv = (const float*)d_in[3];
    float* out = (float*)d_out;

    dim3 pg(M_ / PBM, 3);
    proj_kernel<<<pg, 128>>>(x, Wq, Wk, Wv);
    attn_kernel<<<256, 256>>>(out);
}

// round 4
// speedup vs baseline: 1.6517x; 1.6517x over previous
#include <cuda_runtime.h>

#define B_ 4
#define S_ 2048
#define E_ 1024
#define H_ 128
#define M_ (B_*S_)

#define SCALE_ 11.31370849898476f   // sqrt(128)

#define NSPLIT 4
#define KT 32
#define QTB 64           // q rows per block
#define NQT (S_/QTB)     // 32 q-tiles per batch

// Scratch (device globals: no allocation allowed)
__device__ float g_q[M_*H_];
__device__ float g_k[M_*H_];
__device__ float g_v[M_*H_];
__device__ float g_opart[(size_t)NSPLIT*M_*H_];
__device__ float g_mpart[NSPLIT*M_];
__device__ float g_lpart[NSPLIT*M_];

// ---------------------------------------------------------------------------
// tf32 helpers
// ---------------------------------------------------------------------------
__device__ __forceinline__ unsigned f2tf(float x) {
    unsigned r;
    asm("cvt.rna.tf32.f32 %0, %1;" : "=r"(r) : "f"(x));
    return r;
}
__device__ __forceinline__ void split_tf(float x, unsigned& hi, unsigned& lo) {
    hi = f2tf(x);
    lo = f2tf(x - __uint_as_float(hi));
}

#define MMA_TF32(d, a, b) \
    asm volatile("mma.sync.aligned.m16n8k8.row.col.f32.tf32.tf32.f32 " \
        "{%0,%1,%2,%3}, {%4,%5,%6,%7}, {%8,%9}, {%0,%1,%2,%3};" \
        : "+f"((d)[0]), "+f"((d)[1]), "+f"((d)[2]), "+f"((d)[3]) \
        : "r"((a)[0]), "r"((a)[1]), "r"((a)[2]), "r"((a)[3]), \
          "r"((b)[0]), "r"((b)[1]))

// ---------------------------------------------------------------------------
// Projection GEMM: out[m][h] = sum_e x[m][e]*W[h][e]  (round-1 proven)
// ---------------------------------------------------------------------------
#define PBM 64
#define PBN 128
#define PBK 16

__global__ __launch_bounds__(128) void proj_kernel(
    const float* __restrict__ x,
    const float* __restrict__ Wq,
    const float* __restrict__ Wk,
    const float* __restrict__ Wv)
{
    const float* W;
    float* out;
    float oscale;
    if (blockIdx.y == 0)      { W = Wq; out = g_q; oscale = SCALE_; }
    else if (blockIdx.y == 1) { W = Wk; out = g_k; oscale = 1.0f; }
    else                      { W = Wv; out = g_v; oscale = 1.0f; }

    __shared__ float As[PBK][PBM];
    __shared__ float Bs[PBK][PBN];

    const int tid = threadIdx.x;
    const int ty = tid >> 4;
    const int tx = tid & 15;
    const int m0 = blockIdx.x * PBM;

    float acc[8][8];
#pragma unroll
    for (int i = 0; i < 8; i++)
#pragma unroll
        for (int j = 0; j < 8; j++) acc[i][j] = 0.0f;

    for (int k0 = 0; k0 < E_; k0 += PBK) {
#pragma unroll
        for (int i = 0; i < 2; i++) {
            int f4 = tid + 128 * i;
            int row = f4 >> 2, c4 = f4 & 3;
            float4 v = *(const float4*)&x[(size_t)(m0 + row) * E_ + k0 + c4 * 4];
            As[c4*4+0][row] = v.x; As[c4*4+1][row] = v.y;
            As[c4*4+2][row] = v.z; As[c4*4+3][row] = v.w;
        }
#pragma unroll
        for (int i = 0; i < 4; i++) {
            int f4 = tid + 128 * i;
            int col = f4 >> 2, c4 = f4 & 3;
            float4 v = *(const float4*)&W[(size_t)col * E_ + k0 + c4 * 4];
            Bs[c4*4+0][col] = v.x; Bs[c4*4+1][col] = v.y;
            Bs[c4*4+2][col] = v.z; Bs[c4*4+3][col] = v.w;
        }
        __syncthreads();

#pragma unroll
        for (int kk = 0; kk < PBK; kk++) {
            float a[8], b[8];
            *(float4*)&a[0] = *(const float4*)&As[kk][ty*8];
            *(float4*)&a[4] = *(const float4*)&As[kk][ty*8+4];
            *(float4*)&b[0] = *(const float4*)&Bs[kk][tx*8];
            *(float4*)&b[4] = *(const float4*)&Bs[kk][tx*8+4];
#pragma unroll
            for (int i = 0; i < 8; i++)
#pragma unroll
                for (int j = 0; j < 8; j++)
                    acc[i][j] = fmaf(a[i], b[j], acc[i][j]);
        }
        __syncthreads();
    }

#pragma unroll
    for (int i = 0; i < 8; i++) {
        size_t rbase = (size_t)(m0 + ty*8 + i) * H_ + tx*8;
        float4 r0, r1;
        r0.x = acc[i][0]*oscale; r0.y = acc[i][1]*oscale;
        r0.z = acc[i][2]*oscale; r0.w = acc[i][3]*oscale;
        r1.x = acc[i][4]*oscale; r1.y = acc[i][5]*oscale;
        r1.z = acc[i][6]*oscale; r1.w = acc[i][7]*oscale;
        *(float4*)&out[rbase]     = r0;
        *(float4*)&out[rbase + 4] = r1;
    }
}

// ---------------------------------------------------------------------------
// Flash attention: tf32x3 mma.sync. 128 threads (4 warps), QTB=64, KT=32,
// NSPLIT=4 k-split. Static smem = 64*128*4 + 32*128*4 = 49152 B exactly.
// XOR-swizzled layout (float4-granular): slot c4 of row stored at c4^(row&7).
// Warp w owns q rows [16w, 16w+16).
// ---------------------------------------------------------------------------
__global__ __launch_bounds__(128, 4) void attn_kernel()
{
    __shared__ float Qs[QTB * 128];   // 32KB
    __shared__ float KVs[KT * 128];   // 16KB (K phase, then V phase)

    const int tid  = threadIdx.x;
    const int w    = tid >> 5;
    const int lane = tid & 31;
    const int g    = lane >> 2;   // fragment row group
    const int tig  = lane & 3;    // thread in group

    // serpentine rank: per-SM rank sums ~constant (blocks p,295-p,296+p,511-p)
    const int bx   = blockIdx.x;
    const int wave = bx / 148;
    const int pos  = bx - wave * 148;
    int r;
    if      (wave == 1) r = 295 - pos;
    else if (wave == 3) r = 511 - pos;
    else                r = bx;

    const int qt    = (NQT - 1) - (r >> 4);
    const int sub   = r & 15;
    const int b     = sub & 3;
    const int split = sub >> 2;

    const int nkt = 2 * (qt + 1);
    const int ck  = (nkt + NSPLIT - 1) / NSPLIT;
    const int ks0 = split * ck;
    const int ks1 = min(ks0 + ck, nkt);
    if (ks0 >= ks1) return;          // block-uniform, before any barrier

    const int    qb   = qt * QTB;
    const size_t base = (size_t)b * S_;

    // load Q tile (swizzled). 64 rows x 32 float4.
#pragma unroll
    for (int i = 0; i < 16; i++) {
        int f4 = tid + 128 * i;            // 0..2047
        int row = f4 >> 5, c4 = f4 & 31;
        *(float4*)&Qs[row * 128 + ((c4 ^ (row & 7)) << 2)] =
            *(const float4*)&g_q[(base + qb + row) * H_ + c4 * 4];
    }

    float acc[16][4];
#pragma unroll
    for (int nt = 0; nt < 16; nt++)
#pragma unroll
        for (int j = 0; j < 4; j++) acc[nt][j] = 0.0f;

    float mA = -1e30f, mB = -1e30f, lA = 0.0f, lB = 0.0f;
    const int rA   = 16 * w + g;        // local q row; rA & 7 == g
    const int rowA = qb + rA;           // batch-local q row
    const int rowB = rowA + 8;

    const float* qrowA = &Qs[rA * 128 + tig];
    const float* qrowB = qrowA + 8 * 128;

    for (int kt = ks0; kt < ks1; kt++) {
        const int kb = kt * KT;

        __syncthreads();
        // --- load K tile [32][128] swizzled ---
#pragma unroll
        for (int i = 0; i < 8; i++) {
            int f4 = tid + 128 * i;        // 0..1023
            int row = f4 >> 5, c4 = f4 & 31;
            *(float4*)&KVs[row * 128 + ((c4 ^ (row & 7)) << 2)] =
                *(const float4*)&g_k[(base + kb + row) * H_ + c4 * 4];
        }
        __syncthreads();

        // --- QK^T: S[16 x 32] per warp, 4 n-tiles ---
        float s[4][4];
#pragma unroll
        for (int nt = 0; nt < 4; nt++)
#pragma unroll
            for (int j = 0; j < 4; j++) s[nt][j] = 0.0f;

#pragma unroll
        for (int ks = 0; ks < 16; ks++) {
            const int c0 = ((2 * ks)     ^ g) << 2;   // col 8ks+tig
            const int c1 = ((2 * ks + 1) ^ g) << 2;   // col 8ks+4+tig
            unsigned aH[4], aL[4];
            split_tf(qrowA[c0], aH[0], aL[0]);
            split_tf(qrowB[c0], aH[1], aL[1]);
            split_tf(qrowA[c1], aH[2], aL[2]);
            split_tf(qrowB[c1], aH[3], aL[3]);
#pragma unroll
            for (int nt = 0; nt < 4; nt++) {
                const float* kr = &KVs[(8 * nt + g) * 128 + tig];
                unsigned bH[2], bL[2];
                split_tf(kr[c0], bH[0], bL[0]);
                split_tf(kr[c1], bH[1], bL[1]);
                MMA_TF32(s[nt], aH, bH);
                MMA_TF32(s[nt], aH, bL);
                MMA_TF32(s[nt], aL, bH);
            }
        }

        // --- causal mask (sqrt(H) pre-folded into q) ---
#pragma unroll
        for (int nt = 0; nt < 4; nt++) {
            int c0 = kb + 8 * nt + 2 * tig;
            int c1 = c0 + 1;
            if (c0 > rowA) s[nt][0] = -1e30f;
            if (c1 > rowA) s[nt][1] = -1e30f;
            if (c0 > rowB) s[nt][2] = -1e30f;
            if (c1 > rowB) s[nt][3] = -1e30f;
        }

        // --- online softmax (quad reductions) ---
        float mxA = -1e30f, mxB = -1e30f;
#pragma unroll
        for (int nt = 0; nt < 4; nt++) {
            mxA = fmaxf(mxA, fmaxf(s[nt][0], s[nt][1]));
            mxB = fmaxf(mxB, fmaxf(s[nt][2], s[nt][3]));
        }
        mxA = fmaxf(mxA, __shfl_xor_sync(0xffffffffu, mxA, 1));
        mxA = fmaxf(mxA, __shfl_xor_sync(0xffffffffu, mxA, 2));
        mxB = fmaxf(mxB, __shfl_xor_sync(0xffffffffu, mxB, 1));
        mxB = fmaxf(mxB, __shfl_xor_sync(0xffffffffu, mxB, 2));

        float mAn = fmaxf(mA, mxA), mBn = fmaxf(mB, mxB);
        float cA = __expf(mA - mAn), cB = __expf(mB - mBn);
        float sumA = 0.0f, sumB = 0.0f;
#pragma unroll
        for (int nt = 0; nt < 4; nt++) {
            s[nt][0] = __expf(s[nt][0] - mAn);
            s[nt][1] = __expf(s[nt][1] - mAn);
            s[nt][2] = __expf(s[nt][2] - mBn);
            s[nt][3] = __expf(s[nt][3] - mBn);
            sumA += s[nt][0] + s[nt][1];
            sumB += s[nt][2] + s[nt][3];
        }
        sumA += __shfl_xor_sync(0xffffffffu, sumA, 1);
        sumA += __shfl_xor_sync(0xffffffffu, sumA, 2);
        sumB += __shfl_xor_sync(0xffffffffu, sumB, 1);
        sumB += __shfl_xor_sync(0xffffffffu, sumB, 2);
        lA = lA * cA + sumA;
        lB = lB * cB + sumB;
        mA = mAn; mB = mBn;
#pragma unroll
        for (int nt = 0; nt < 16; nt++) {
            acc[nt][0] *= cA; acc[nt][1] *= cA;
            acc[nt][2] *= cB; acc[nt][3] *= cB;
        }

        __syncthreads();
        // --- load V tile [32][128] swizzled (same buffer) ---
#pragma unroll
        for (int i = 0; i < 8; i++) {
            int f4 = tid + 128 * i;
            int row = f4 >> 5, c4 = f4 & 31;
            *(float4*)&KVs[row * 128 + ((c4 ^ (row & 7)) << 2)] =
                *(const float4*)&g_v[(base + kb + row) * H_ + c4 * 4];
        }
        __syncthreads();

        // --- AV: O[16 x 128] += P[16 x 32] * V[32 x 128] ---
        const int srcE = (lane & ~3) | (tig >> 1);
        const int srcO = srcE + 2;
        const int gh   = g >> 2;
        const int gl   = g & 3;
#pragma unroll
        for (int ka = 0; ka < 4; ka++) {
            // A-frag from P tile ka via quad shuffles
            float e, o, a0f, a1f, a2f, a3f;
            e = __shfl_sync(0xffffffffu, s[ka][0], srcE);
            o = __shfl_sync(0xffffffffu, s[ka][1], srcE);
            a0f = (tig & 1) ? o : e;
            e = __shfl_sync(0xffffffffu, s[ka][0], srcO);
            o = __shfl_sync(0xffffffffu, s[ka][1], srcO);
            a2f = (tig & 1) ? o : e;
            e = __shfl_sync(0xffffffffu, s[ka][2], srcE);
            o = __shfl_sync(0xffffffffu, s[ka][3], srcE);
            a1f = (tig & 1) ? o : e;
            e = __shfl_sync(0xffffffffu, s[ka][2], srcO);
            o = __shfl_sync(0xffffffffu, s[ka][3], srcO);
            a3f = (tig & 1) ? o : e;

            unsigned aH[4], aL[4];
            split_tf(a0f, aH[0], aL[0]);
            split_tf(a1f, aH[1], aL[1]);
            split_tf(a2f, aH[2], aL[2]);
            split_tf(a3f, aH[3], aL[3]);

            const float* v0 = &KVs[(8 * ka + tig) * 128 + gl];       // row&7 = tig
            const float* v1 = &KVs[(8 * ka + tig + 4) * 128 + gl];   // row&7 = tig+4
#pragma unroll
            for (int nt = 0; nt < 16; nt++) {
                const int o0 = ((2 * nt + gh) ^ tig) << 2;
                const int o1 = o0 ^ 16;                  // xor (tig+4) = o0 ^ (4<<2)
                unsigned bH[2], bL[2];
                split_tf(v0[o0], bH[0], bL[0]);
                split_tf(v1[o1], bH[1], bL[1]);
                MMA_TF32(acc[nt], aH, bH);
                MMA_TF32(acc[nt], aH, bL);
                MMA_TF32(acc[nt], aL, bH);
            }
        }
    }

    // --- epilogue: store partials (unnormalized o, m, l) ---
    const size_t growA = (size_t)split * M_ + base + rowA;
    const size_t growB = growA + 8;
#pragma unroll
    for (int nt = 0; nt < 16; nt++) {
        *(float2*)&g_opart[growA * H_ + 8 * nt + 2 * tig] =
            make_float2(acc[nt][0], acc[nt][1]);
        *(float2*)&g_opart[growB * H_ + 8 * nt + 2 * tig] =
            make_float2(acc[nt][2], acc[nt][3]);
    }
    if (tig == 0) {
        g_mpart[growA] = mA; g_lpart[growA] = lA;
        g_mpart[growB] = mB; g_lpart[growB] = lB;
    }
}

// ---------------------------------------------------------------------------
// Combine kernel: merge NSPLIT partials per row.
// ---------------------------------------------------------------------------
__global__ __launch_bounds__(256) void combine_kernel(float* __restrict__ out)
{
    const int t   = blockIdx.x * 256 + threadIdx.x;   // 0..262143
    const int row = t >> 5;                           // 0..8191
    const int h   = (t & 31) * 4;

    const int qt  = (row & (S_ - 1)) >> 6;            // QTB=64
    const int nkt = 2 * (qt + 1);
    const int ck  = (nkt + NSPLIT - 1) / NSPLIT;

    float ms[NSPLIT];
    float M = -1e30f;
#pragma unroll
    for (int sp = 0; sp < NSPLIT; sp++) {
        bool valid = (sp * ck < nkt);
        ms[sp] = valid ? g_mpart[sp * M_ + row] : -1e30f;
        M = fmaxf(M, ms[sp]);
    }

    float L = 0.0f;
    float4 o = make_float4(0.f, 0.f, 0.f, 0.f);
#pragma unroll
    for (int sp = 0; sp < NSPLIT; sp++) {
        if (sp * ck < nkt) {
            float e = __expf(ms[sp] - M);
            L += e * g_lpart[sp * M_ + row];
            float4 v = *(const float4*)&g_opart[((size_t)sp * M_ + row) * H_ + h];
            o.x += e * v.x; o.y += e * v.y; o.z += e * v.z; o.w += e * v.w;
        }
    }
    float inv = 1.0f / L;
    float4 rr = make_float4(o.x * inv, o.y * inv, o.z * inv, o.w * inv);
    *(float4*)&out[(size_t)row * H_ + h] = rr;
}

// ---------------------------------------------------------------------------
extern "C" void kernel_launch(void* const* d_in, const int* in_sizes, int n_in,
                              void* d_out, int out_size)
{
    const float* x  = (const float*)d_in[0];
    const float* Wq = (const float*)d_in[1];
    const float* Wk = (const float*)d_in[2];
    const float* Wv = (const float*)d_in[3];
    float* out = (float*)d_out;

    dim3 pg(M_ / PBM, 3);
    proj_kernel<<<pg, 128>>>(x, Wq, Wk, Wv);
    attn_kernel<<<NSPLIT * B_ * NQT, 128>>>();
    combine_kernel<<<(M_ * H_ / 4) / 256, 256>>>(out);
}

// round 5
// speedup vs baseline: 1.7422x; 1.0548x over previous
#include <cuda_runtime.h>

#define B_ 4
#define S_ 2048
#define E_ 1024
#define H_ 128
#define M_ (B_*S_)

#define SCALE_ 11.31370849898476f   // sqrt(128)

#define NSPLIT 4
#define KT 32
#define QTB 64           // q rows per block
#define NQT (S_/QTB)     // 32 q-tiles per batch

// Scratch (device globals: no allocation allowed)
__device__ float g_q[M_*H_];
__device__ float g_k[M_*H_];
__device__ float g_v[M_*H_];
__device__ float g_opart[(size_t)NSPLIT*M_*H_];
__device__ float g_mpart[NSPLIT*M_];
__device__ float g_lpart[NSPLIT*M_];

// ---------------------------------------------------------------------------
// tf32 helpers
// ---------------------------------------------------------------------------
__device__ __forceinline__ unsigned f2tf(float x) {
    unsigned r;
    asm("cvt.rna.tf32.f32 %0, %1;" : "=r"(r) : "f"(x));
    return r;
}
__device__ __forceinline__ void split_tf(float x, unsigned& hi, unsigned& lo) {
    hi = f2tf(x);
    lo = f2tf(x - __uint_as_float(hi));
}

#define MMA_TF32(d, a, b) \
    asm volatile("mma.sync.aligned.m16n8k8.row.col.f32.tf32.tf32.f32 " \
        "{%0,%1,%2,%3}, {%4,%5,%6,%7}, {%8,%9}, {%0,%1,%2,%3};" \
        : "+f"((d)[0]), "+f"((d)[1]), "+f"((d)[2]), "+f"((d)[3]) \
        : "r"((a)[0]), "r"((a)[1]), "r"((a)[2]), "r"((a)[3]), \
          "r"((b)[0]), "r"((b)[1]))

// ---------------------------------------------------------------------------
// Projection GEMM via tf32x3 mma: out[m][h] = sum_e x[m][e]*W[h][e]
// BM=128, BN=128(=H), BK=32. 256 threads = 8 warps (4m x 2n), warp tile 32x64.
// Same XOR-swizzled smem + fragment addressing as the attention QK^T.
// smem = 2 * 128*32*4 = 32KB static.
// ---------------------------------------------------------------------------
__global__ __launch_bounds__(256, 2) void proj_kernel(
    const float* __restrict__ x,
    const float* __restrict__ Wq,
    const float* __restrict__ Wk,
    const float* __restrict__ Wv)
{
    const float* W;
    float* out;
    float oscale;
    if (blockIdx.y == 0)      { W = Wq; out = g_q; oscale = SCALE_; }
    else if (blockIdx.y == 1) { W = Wk; out = g_k; oscale = 1.0f; }
    else                      { W = Wv; out = g_v; oscale = 1.0f; }

    __shared__ float Xs[128 * 32];   // 16KB, swizzled
    __shared__ float Ws[128 * 32];   // 16KB, swizzled

    const int tid  = threadIdx.x;
    const int w    = tid >> 5;
    const int lane = tid & 31;
    const int g    = lane >> 2;
    const int tig  = lane & 3;

    const int m0 = blockIdx.x * 128;
    const int mw = (w >> 1) * 32;    // warp m-base within block
    const int nw = (w & 1) * 64;     // warp n-base

    // load indices (4 float4 each for X and W per thread)
    const int lrow = tid >> 1;                 // two threads per row? no:
    // f4 = tid + 256*i ; row = f4>>3 (0..127), c4 = f4&7
    float acc[2][8][4];
#pragma unroll
    for (int i = 0; i < 2; i++)
#pragma unroll
        for (int j = 0; j < 8; j++)
#pragma unroll
            for (int c = 0; c < 4; c++) acc[i][j][c] = 0.0f;
    (void)lrow;

    for (int k0 = 0; k0 < E_; k0 += 32) {
        __syncthreads();
        // --- load X tile [128][32] and W tile [128][32], swizzled ---
#pragma unroll
        for (int i = 0; i < 4; i++) {
            int f4 = tid + 256 * i;          // 0..1023
            int row = f4 >> 3, c4 = f4 & 7;
            int saddr = row * 32 + ((c4 ^ (row & 7)) << 2);
            *(float4*)&Xs[saddr] =
                *(const float4*)&x[(size_t)(m0 + row) * E_ + k0 + c4 * 4];
            *(float4*)&Ws[saddr] =
                *(const float4*)&W[(size_t)row * E_ + k0 + c4 * 4];
        }
        __syncthreads();

#pragma unroll
        for (int kk = 0; kk < 4; kk++) {
            const int s0 = ((2 * kk)     ^ g) << 2;   // k = 8kk + tig
            const int s1 = ((2 * kk + 1) ^ g) << 2;   // k = 8kk + 4 + tig

            unsigned aH[2][4], aL[2][4];
#pragma unroll
            for (int i = 0; i < 2; i++) {
                const float* xr = &Xs[(mw + 16 * i + g) * 32 + tig];
                split_tf(xr[s0],           aH[i][0], aL[i][0]);
                split_tf(xr[8 * 32 + s0],  aH[i][1], aL[i][1]);
                split_tf(xr[s1],           aH[i][2], aL[i][2]);
                split_tf(xr[8 * 32 + s1],  aH[i][3], aL[i][3]);
            }
#pragma unroll
            for (int j = 0; j < 8; j++) {
                const float* wr = &Ws[(nw + 8 * j + g) * 32 + tig];
                unsigned bH[2], bL[2];
                split_tf(wr[s0], bH[0], bL[0]);
                split_tf(wr[s1], bH[1], bL[1]);
#pragma unroll
                for (int i = 0; i < 2; i++) {
                    MMA_TF32(acc[i][j], aH[i], bH);
                    MMA_TF32(acc[i][j], aH[i], bL);
                    MMA_TF32(acc[i][j], aL[i], bH);
                }
            }
        }
    }

    // --- epilogue: C rows m0+mw+16i+{g, g+8}, cols nw+8j+2tig(+1) ---
#pragma unroll
    for (int i = 0; i < 2; i++) {
        const size_t r0 = (size_t)(m0 + mw + 16 * i + g);
#pragma unroll
        for (int j = 0; j < 8; j++) {
            const int col = nw + 8 * j + 2 * tig;
            *(float2*)&out[r0 * H_ + col] =
                make_float2(acc[i][j][0] * oscale, acc[i][j][1] * oscale);
            *(float2*)&out[(r0 + 8) * H_ + col] =
                make_float2(acc[i][j][2] * oscale, acc[i][j][3] * oscale);
        }
    }
}

// ---------------------------------------------------------------------------
// Flash attention: tf32x3 mma.sync. 128 threads (4 warps), QTB=64, KT=32,
// NSPLIT=4 k-split. Static smem = 49152 B exactly. (unchanged from round 4)
// ---------------------------------------------------------------------------
__global__ __launch_bounds__(128, 4) void attn_kernel()
{
    __shared__ float Qs[QTB * 128];   // 32KB
    __shared__ float KVs[KT * 128];   // 16KB (K phase, then V phase)

    const int tid  = threadIdx.x;
    const int w    = tid >> 5;
    const int lane = tid & 31;
    const int g    = lane >> 2;
    const int tig  = lane & 3;

    const int bx   = blockIdx.x;
    const int wave = bx / 148;
    const int pos  = bx - wave * 148;
    int r;
    if      (wave == 1) r = 295 - pos;
    else if (wave == 3) r = 511 - pos;
    else                r = bx;

    const int qt    = (NQT - 1) - (r >> 4);
    const int sub   = r & 15;
    const int b     = sub & 3;
    const int split = sub >> 2;

    const int nkt = 2 * (qt + 1);
    const int ck  = (nkt + NSPLIT - 1) / NSPLIT;
    const int ks0 = split * ck;
    const int ks1 = min(ks0 + ck, nkt);
    if (ks0 >= ks1) return;

    const int    qb   = qt * QTB;
    const size_t base = (size_t)b * S_;

#pragma unroll
    for (int i = 0; i < 16; i++) {
        int f4 = tid + 128 * i;
        int row = f4 >> 5, c4 = f4 & 31;
        *(float4*)&Qs[row * 128 + ((c4 ^ (row & 7)) << 2)] =
            *(const float4*)&g_q[(base + qb + row) * H_ + c4 * 4];
    }

    float acc[16][4];
#pragma unroll
    for (int nt = 0; nt < 16; nt++)
#pragma unroll
        for (int j = 0; j < 4; j++) acc[nt][j] = 0.0f;

    float mA = -1e30f, mB = -1e30f, lA = 0.0f, lB = 0.0f;
    const int rA   = 16 * w + g;
    const int rowA = qb + rA;
    const int rowB = rowA + 8;

    const float* qrowA = &Qs[rA * 128 + tig];
    const float* qrowB = qrowA + 8 * 128;

    for (int kt = ks0; kt < ks1; kt++) {
        const int kb = kt * KT;

        __syncthreads();
#pragma unroll
        for (int i = 0; i < 8; i++) {
            int f4 = tid + 128 * i;
            int row = f4 >> 5, c4 = f4 & 31;
            *(float4*)&KVs[row * 128 + ((c4 ^ (row & 7)) << 2)] =
                *(const float4*)&g_k[(base + kb + row) * H_ + c4 * 4];
        }
        __syncthreads();

        float s[4][4];
#pragma unroll
        for (int nt = 0; nt < 4; nt++)
#pragma unroll
            for (int j = 0; j < 4; j++) s[nt][j] = 0.0f;

#pragma unroll
        for (int ks = 0; ks < 16; ks++) {
            const int c0 = ((2 * ks)     ^ g) << 2;
            const int c1 = ((2 * ks + 1) ^ g) << 2;
            unsigned aH[4], aL[4];
            split_tf(qrowA[c0], aH[0], aL[0]);
            split_tf(qrowB[c0], aH[1], aL[1]);
            split_tf(qrowA[c1], aH[2], aL[2]);
            split_tf(qrowB[c1], aH[3], aL[3]);
#pragma unroll
            for (int nt = 0; nt < 4; nt++) {
                const float* kr = &KVs[(8 * nt + g) * 128 + tig];
                unsigned bH[2], bL[2];
                split_tf(kr[c0], bH[0], bL[0]);
                split_tf(kr[c1], bH[1], bL[1]);
                MMA_TF32(s[nt], aH, bH);
                MMA_TF32(s[nt], aH, bL);
                MMA_TF32(s[nt], aL, bH);
            }
        }

#pragma unroll
        for (int nt = 0; nt < 4; nt++) {
            int c0 = kb + 8 * nt + 2 * tig;
            int c1 = c0 + 1;
            if (c0 > rowA) s[nt][0] = -1e30f;
            if (c1 > rowA) s[nt][1] = -1e30f;
            if (c0 > rowB) s[nt][2] = -1e30f;
            if (c1 > rowB) s[nt][3] = -1e30f;
        }

        float mxA = -1e30f, mxB = -1e30f;
#pragma unroll
        for (int nt = 0; nt < 4; nt++) {
            mxA = fmaxf(mxA, fmaxf(s[nt][0], s[nt][1]));
            mxB = fmaxf(mxB, fmaxf(s[nt][2], s[nt][3]));
        }
        mxA = fmaxf(mxA, __shfl_xor_sync(0xffffffffu, mxA, 1));
        mxA = fmaxf(mxA, __shfl_xor_sync(0xffffffffu, mxA, 2));
        mxB = fmaxf(mxB, __shfl_xor_sync(0xffffffffu, mxB, 1));
        mxB = fmaxf(mxB, __shfl_xor_sync(0xffffffffu, mxB, 2));

        float mAn = fmaxf(mA, mxA), mBn = fmaxf(mB, mxB);
        float cA = __expf(mA - mAn), cB = __expf(mB - mBn);
        float sumA = 0.0f, sumB = 0.0f;
#pragma unroll
        for (int nt = 0; nt < 4; nt++) {
            s[nt][0] = __expf(s[nt][0] - mAn);
            s[nt][1] = __expf(s[nt][1] - mAn);
            s[nt][2] = __expf(s[nt][2] - mBn);
            s[nt][3] = __expf(s[nt][3] - mBn);
            sumA += s[nt][0] + s[nt][1];
            sumB += s[nt][2] + s[nt][3];
        }
        sumA += __shfl_xor_sync(0xffffffffu, sumA, 1);
        sumA += __shfl_xor_sync(0xffffffffu, sumA, 2);
        sumB += __shfl_xor_sync(0xffffffffu, sumB, 1);
        sumB += __shfl_xor_sync(0xffffffffu, sumB, 2);
        lA = lA * cA + sumA;
        lB = lB * cB + sumB;
        mA = mAn; mB = mBn;
#pragma unroll
        for (int nt = 0; nt < 16; nt++) {
            acc[nt][0] *= cA; acc[nt][1] *= cA;
            acc[nt][2] *= cB; acc[nt][3] *= cB;
        }

        __syncthreads();
#pragma unroll
        for (int i = 0; i < 8; i++) {
            int f4 = tid + 128 * i;
            int row = f4 >> 5, c4 = f4 & 31;
            *(float4*)&KVs[row * 128 + ((c4 ^ (row & 7)) << 2)] =
                *(const float4*)&g_v[(base + kb + row) * H_ + c4 * 4];
        }
        __syncthreads();

        const int srcE = (lane & ~3) | (tig >> 1);
        const int srcO = srcE + 2;
        const int gh   = g >> 2;
        const int gl   = g & 3;
#pragma unroll
        for (int ka = 0; ka < 4; ka++) {
            float e, o, a0f, a1f, a2f, a3f;
            e = __shfl_sync(0xffffffffu, s[ka][0], srcE);
            o = __shfl_sync(0xffffffffu, s[ka][1], srcE);
            a0f = (tig & 1) ? o : e;
            e = __shfl_sync(0xffffffffu, s[ka][0], srcO);
            o = __shfl_sync(0xffffffffu, s[ka][1], srcO);
            a2f = (tig & 1) ? o : e;
            e = __shfl_sync(0xffffffffu, s[ka][2], srcE);
            o = __shfl_sync(0xffffffffu, s[ka][3], srcE);
            a1f = (tig & 1) ? o : e;
            e = __shfl_sync(0xffffffffu, s[ka][2], srcO);
            o = __shfl_sync(0xffffffffu, s[ka][3], srcO);
            a3f = (tig & 1) ? o : e;

            unsigned aH[4], aL[4];
            split_tf(a0f, aH[0], aL[0]);
            split_tf(a1f, aH[1], aL[1]);
            split_tf(a2f, aH[2], aL[2]);
            split_tf(a3f, aH[3], aL[3]);

            const float* v0 = &KVs[(8 * ka + tig) * 128 + gl];
            const float* v1 = &KVs[(8 * ka + tig + 4) * 128 + gl];
#pragma unroll
            for (int nt = 0; nt < 16; nt++) {
                const int o0 = ((2 * nt + gh) ^ tig) << 2;
                const int o1 = o0 ^ 16;
                unsigned bH[2], bL[2];
                split_tf(v0[o0], bH[0], bL[0]);
                split_tf(v1[o1], bH[1], bL[1]);
                MMA_TF32(acc[nt], aH, bH);
                MMA_TF32(acc[nt], aH, bL);
                MMA_TF32(acc[nt], aL, bH);
            }
        }
    }

    const size_t growA = (size_t)split * M_ + base + rowA;
    const size_t growB = growA + 8;
#pragma unroll
    for (int nt = 0; nt < 16; nt++) {
        *(float2*)&g_opart[growA * H_ + 8 * nt + 2 * tig] =
            make_float2(acc[nt][0], acc[nt][1]);
        *(float2*)&g_opart[growB * H_ + 8 * nt + 2 * tig] =
            make_float2(acc[nt][2], acc[nt][3]);
    }
    if (tig == 0) {
        g_mpart[growA] = mA; g_lpart[growA] = lA;
        g_mpart[growB] = mB; g_lpart[growB] = lB;
    }
}

// ---------------------------------------------------------------------------
// Combine kernel: merge NSPLIT partials per row.
// ---------------------------------------------------------------------------
__global__ __launch_bounds__(256) void combine_kernel(float* __restrict__ out)
{
    const int t   = blockIdx.x * 256 + threadIdx.x;
    const int row = t >> 5;
    const int h   = (t & 31) * 4;

    const int qt  = (row & (S_ - 1)) >> 6;            // QTB=64
    const int nkt = 2 * (qt + 1);
    const int ck  = (nkt + NSPLIT - 1) / NSPLIT;

    float ms[NSPLIT];
    float M = -1e30f;
#pragma unroll
    for (int sp = 0; sp < NSPLIT; sp++) {
        bool valid = (sp * ck < nkt);
        ms[sp] = valid ? g_mpart[sp * M_ + row] : -1e30f;
        M = fmaxf(M, ms[sp]);
    }

    float L = 0.0f;
    float4 o = make_float4(0.f, 0.f, 0.f, 0.f);
#pragma unroll
    for (int sp = 0; sp < NSPLIT; sp++) {
        if (sp * ck < nkt) {
            float e = __expf(ms[sp] - M);
            L += e * g_lpart[sp * M_ + row];
            float4 v = *(const float4*)&g_opart[((size_t)sp * M_ + row) * H_ + h];
            o.x += e * v.x; o.y += e * v.y; o.z += e * v.z; o.w += e * v.w;
        }
    }
    float inv = 1.0f / L;
    float4 rr = make_float4(o.x * inv, o.y * inv, o.z * inv, o.w * inv);
    *(float4*)&out[(size_t)row * H_ + h] = rr;
}

// ---------------------------------------------------------------------------
extern "C" void kernel_launch(void* const* d_in, const int* in_sizes, int n_in,
                              void* d_out, int out_size)
{
    const float* x  = (const float*)d_in[0];
    const float* Wq = (const float*)d_in[1];
    const float* Wk = (const float*)d_in[2];
    const float* Wv = (const float*)d_in[3];
    float* out = (float*)d_out;

    dim3 pg(M_ / 128, 3);
    proj_kernel<<<pg, 256>>>(x, Wq, Wk, Wv);
    attn_kernel<<<NSPLIT * B_ * NQT, 128>>>();
    combine_kernel<<<(M_ * H_ / 4) / 256, 256>>>(out);
}

// round 6
// speedup vs baseline: 1.7642x; 1.0127x over previous
#include <cuda_runtime.h>

#define B_ 4
#define S_ 2048
#define E_ 1024
#define H_ 128
#define M_ (B_*S_)

#define SCALE_ 11.31370849898476f   // sqrt(128)

#define NSPLIT 4
#define KT 32
#define QTB 64           // q rows per block
#define NQT (S_/QTB)     // 32 q-tiles per batch

// Scratch (device globals: no allocation allowed)
__device__ float g_q[M_*H_];
__device__ float g_k[M_*H_];
__device__ float g_v[M_*H_];
__device__ float g_opart[(size_t)NSPLIT*M_*H_];
__device__ float g_mpart[NSPLIT*M_];
__device__ float g_lpart[NSPLIT*M_];

// ---------------------------------------------------------------------------
// tf32 helpers
// ---------------------------------------------------------------------------
__device__ __forceinline__ unsigned f2tf(float x) {
    unsigned r;
    asm("cvt.rna.tf32.f32 %0, %1;" : "=r"(r) : "f"(x));
    return r;
}
__device__ __forceinline__ void split_tf(float x, unsigned& hi, unsigned& lo) {
    hi = f2tf(x);
    lo = f2tf(x - __uint_as_float(hi));
}

#define MMA_TF32(d, a, b) \
    asm volatile("mma.sync.aligned.m16n8k8.row.col.f32.tf32.tf32.f32 " \
        "{%0,%1,%2,%3}, {%4,%5,%6,%7}, {%8,%9}, {%0,%1,%2,%3};" \
        : "+f"((d)[0]), "+f"((d)[1]), "+f"((d)[2]), "+f"((d)[3]) \
        : "r"((a)[0]), "r"((a)[1]), "r"((a)[2]), "r"((a)[3]), \
          "r"((b)[0]), "r"((b)[1]))

#define CP_ASYNC16(dst, src) \
    asm volatile("cp.async.cg.shared.global [%0], [%1], 16;\n" \
        :: "r"(dst), "l"(src))
#define CP_COMMIT() asm volatile("cp.async.commit_group;\n" ::: "memory")
#define CP_WAIT(n)  asm volatile("cp.async.wait_group %0;\n" :: "n"(n) : "memory")

// ---------------------------------------------------------------------------
// Projection GEMM via tf32x3 mma: out[m][h] = sum_e x[m][e]*W[h][e]
// BM=128, BN=128(=H), BK=16, double-buffered cp.async pipeline.
// 256 threads = 8 warps (4m x 2n), warp tile 32x64.
// smem = 2 buffers * (128+128)*16*4 = 32KB static.
// Swizzle: float4 slot c4 of row r stored at c4 ^ ((r>>1)&3). For all
// fragment rows the swizzle collapses to the per-thread constant (g>>1)&3.
// ---------------------------------------------------------------------------
__global__ __launch_bounds__(256, 2) void proj_kernel(
    const float* __restrict__ x,
    const float* __restrict__ Wq,
    const float* __restrict__ Wk,
    const float* __restrict__ Wv)
{
    const float* W;
    float* out;
    float oscale;
    if (blockIdx.y == 0)      { W = Wq; out = g_q; oscale = SCALE_; }
    else if (blockIdx.y == 1) { W = Wk; out = g_k; oscale = 1.0f; }
    else                      { W = Wv; out = g_v; oscale = 1.0f; }

    __shared__ float Xs[2][128 * 16];   // 16KB
    __shared__ float Ws[2][128 * 16];   // 16KB

    const int tid  = threadIdx.x;
    const int w    = tid >> 5;
    const int lane = tid & 31;
    const int g    = lane >> 2;
    const int tig  = lane & 3;

    const int m0 = blockIdx.x * 128;
    const int mw = (w >> 1) * 32;    // warp m-base
    const int nw = (w & 1) * 64;     // warp n-base

    // per-thread load slots (2 float4 of X, 2 of W)
    const int f4a   = tid;                 // 0..255
    const int f4b   = tid + 256;           // 256..511
    const int rowa  = f4a >> 2, c4a = f4a & 3;
    const int rowb  = f4b >> 2, c4b = f4b & 3;
    const int soffa = rowa * 16 + ((c4a ^ ((rowa >> 1) & 3)) << 2);
    const int soffb = rowb * 16 + ((c4b ^ ((rowb >> 1) & 3)) << 2);
    const float* xsrca = &x[(size_t)(m0 + rowa) * E_ + c4a * 4];
    const float* xsrcb = &x[(size_t)(m0 + rowb) * E_ + c4b * 4];
    const float* wsrca = &W[(size_t)rowa * E_ + c4a * 4];
    const float* wsrcb = &W[(size_t)rowb * E_ + c4b * 4];

    unsigned xs_u32[2], ws_u32[2];
#pragma unroll
    for (int bb = 0; bb < 2; bb++) {
        xs_u32[bb] = (unsigned)__cvta_generic_to_shared(&Xs[bb][0]);
        ws_u32[bb] = (unsigned)__cvta_generic_to_shared(&Ws[bb][0]);
    }

    float acc[2][8][4];
#pragma unroll
    for (int i = 0; i < 2; i++)
#pragma unroll
        for (int j = 0; j < 8; j++)
#pragma unroll
            for (int c = 0; c < 4; c++) acc[i][j][c] = 0.0f;

    // fragment swizzle constant and column offsets
    const int sw = (g >> 1) & 3;
    const int o0k0 = ((0 ^ sw) << 2);   // kk=0, cols tig / tig+4 group 0
    const int o1k0 = ((1 ^ sw) << 2);
    const int o0k1 = ((2 ^ sw) << 2);   // kk=1
    const int o1k1 = ((3 ^ sw) << 2);

    const float* xfr[2];
    xfr[0] = &Xs[0][(mw + g) * 16 + tig];
    xfr[1] = &Xs[1][(mw + g) * 16 + tig];
    const float* wfr[2];
    wfr[0] = &Ws[0][(nw + g) * 16 + tig];
    wfr[1] = &Ws[1][(nw + g) * 16 + tig];

    // prologue: load tile 0 into buffer 0
    CP_ASYNC16(xs_u32[0] + soffa * 4, xsrca);
    CP_ASYNC16(ws_u32[0] + soffa * 4, wsrca);
    CP_ASYNC16(xs_u32[0] + soffb * 4, xsrcb);
    CP_ASYNC16(ws_u32[0] + soffb * 4, wsrcb);
    CP_COMMIT();

    for (int t = 0; t < E_ / 16; t++) {
        const int buf = t & 1;
        if (t + 1 < E_ / 16) {
            const int nb = (t + 1) & 1;
            const int ko = (t + 1) * 16;
            CP_ASYNC16(xs_u32[nb] + soffa * 4, xsrca + ko);
            CP_ASYNC16(ws_u32[nb] + soffa * 4, wsrca + ko);
            CP_ASYNC16(xs_u32[nb] + soffb * 4, xsrcb + ko);
            CP_ASYNC16(ws_u32[nb] + soffb * 4, wsrcb + ko);
            CP_COMMIT();
            CP_WAIT(1);
        } else {
            CP_WAIT(0);
        }
        __syncthreads();

#pragma unroll
        for (int kk = 0; kk < 2; kk++) {
            const int s0 = kk ? o0k1 : o0k0;
            const int s1 = kk ? o1k1 : o1k0;

            unsigned aH[2][4], aL[2][4];
#pragma unroll
            for (int i = 0; i < 2; i++) {
                const float* xr = xfr[buf] + 16 * 16 * i;   // rows mw+16i+g
                split_tf(xr[s0],            aH[i][0], aL[i][0]);
                split_tf(xr[8 * 16 + s0],   aH[i][1], aL[i][1]);
                split_tf(xr[s1],            aH[i][2], aL[i][2]);
                split_tf(xr[8 * 16 + s1],   aH[i][3], aL[i][3]);
            }
#pragma unroll
            for (int j = 0; j < 8; j++) {
                const float* wr = wfr[buf] + 8 * 16 * j;    // rows nw+8j+g
                unsigned bH[2], bL[2];
                split_tf(wr[s0], bH[0], bL[0]);
                split_tf(wr[s1], bH[1], bL[1]);
#pragma unroll
                for (int i = 0; i < 2; i++) {
                    MMA_TF32(acc[i][j], aH[i], bH);
                    MMA_TF32(acc[i][j], aH[i], bL);
                    MMA_TF32(acc[i][j], aL[i], bH);
                }
            }
        }
        __syncthreads();
    }

    // --- epilogue: C rows m0+mw+16i+{g, g+8}, cols nw+8j+2tig(+1) ---
#pragma unroll
    for (int i = 0; i < 2; i++) {
        const size_t r0 = (size_t)(m0 + mw + 16 * i + g);
#pragma unroll
        for (int j = 0; j < 8; j++) {
            const int col = nw + 8 * j + 2 * tig;
            *(float2*)&out[r0 * H_ + col] =
                make_float2(acc[i][j][0] * oscale, acc[i][j][1] * oscale);
            *(float2*)&out[(r0 + 8) * H_ + col] =
                make_float2(acc[i][j][2] * oscale, acc[i][j][3] * oscale);
        }
    }
}

// ---------------------------------------------------------------------------
// Flash attention: tf32x3 mma.sync. 128 threads (4 warps), QTB=64, KT=32,
// NSPLIT=4 k-split. Static smem = 49152 B exactly. (unchanged, passing)
// ---------------------------------------------------------------------------
__global__ __launch_bounds__(128, 4) void attn_kernel()
{
    __shared__ float Qs[QTB * 128];   // 32KB
    __shared__ float KVs[KT * 128];   // 16KB (K phase, then V phase)

    const int tid  = threadIdx.x;
    const int w    = tid >> 5;
    const int lane = tid & 31;
    const int g    = lane >> 2;
    const int tig  = lane & 3;

    const int bx   = blockIdx.x;
    const int wave = bx / 148;
    const int pos  = bx - wave * 148;
    int r;
    if      (wave == 1) r = 295 - pos;
    else if (wave == 3) r = 511 - pos;
    else                r = bx;

    const int qt    = (NQT - 1) - (r >> 4);
    const int sub   = r & 15;
    const int b     = sub & 3;
    const int split = sub >> 2;

    const int nkt = 2 * (qt + 1);
    const int ck  = (nkt + NSPLIT - 1) / NSPLIT;
    const int ks0 = split * ck;
    const int ks1 = min(ks0 + ck, nkt);
    if (ks0 >= ks1) return;

    const int    qb   = qt * QTB;
    const size_t base = (size_t)b * S_;

#pragma unroll
    for (int i = 0; i < 16; i++) {
        int f4 = tid + 128 * i;
        int row = f4 >> 5, c4 = f4 & 31;
        *(float4*)&Qs[row * 128 + ((c4 ^ (row & 7)) << 2)] =
            *(const float4*)&g_q[(base + qb + row) * H_ + c4 * 4];
    }

    float acc[16][4];
#pragma unroll
    for (int nt = 0; nt < 16; nt++)
#pragma unroll
        for (int j = 0; j < 4; j++) acc[nt][j] = 0.0f;

    float mA = -1e30f, mB = -1e30f, lA = 0.0f, lB = 0.0f;
    const int rA   = 16 * w + g;
    const int rowA = qb + rA;
    const int rowB = rowA + 8;

    const float* qrowA = &Qs[rA * 128 + tig];
    const float* qrowB = qrowA + 8 * 128;

    for (int kt = ks0; kt < ks1; kt++) {
        const int kb = kt * KT;

        __syncthreads();
#pragma unroll
        for (int i = 0; i < 8; i++) {
            int f4 = tid + 128 * i;
            int row = f4 >> 5, c4 = f4 & 31;
            *(float4*)&KVs[row * 128 + ((c4 ^ (row & 7)) << 2)] =
                *(const float4*)&g_k[(base + kb + row) * H_ + c4 * 4];
        }
        __syncthreads();

        float s[4][4];
#pragma unroll
        for (int nt = 0; nt < 4; nt++)
#pragma unroll
            for (int j = 0; j < 4; j++) s[nt][j] = 0.0f;

#pragma unroll
        for (int ks = 0; ks < 16; ks++) {
            const int c0 = ((2 * ks)     ^ g) << 2;
            const int c1 = ((2 * ks + 1) ^ g) << 2;
            unsigned aH[4], aL[4];
            split_tf(qrowA[c0], aH[0], aL[0]);
            split_tf(qrowB[c0], aH[1], aL[1]);
            split_tf(qrowA[c1], aH[2], aL[2]);
            split_tf(qrowB[c1], aH[3], aL[3]);
#pragma unroll
            for (int nt = 0; nt < 4; nt++) {
                const float* kr = &KVs[(8 * nt + g) * 128 + tig];
                unsigned bH[2], bL[2];
                split_tf(kr[c0], bH[0], bL[0]);
                split_tf(kr[c1], bH[1], bL[1]);
                MMA_TF32(s[nt], aH, bH);
                MMA_TF32(s[nt], aH, bL);
                MMA_TF32(s[nt], aL, bH);
            }
        }

#pragma unroll
        for (int nt = 0; nt < 4; nt++) {
            int c0 = kb + 8 * nt + 2 * tig;
            int c1 = c0 + 1;
            if (c0 > rowA) s[nt][0] = -1e30f;
            if (c1 > rowA) s[nt][1] = -1e30f;
            if (c0 > rowB) s[nt][2] = -1e30f;
            if (c1 > rowB) s[nt][3] = -1e30f;
        }

        float mxA = -1e30f, mxB = -1e30f;
#pragma unroll
        for (int nt = 0; nt < 4; nt++) {
            mxA = fmaxf(mxA, fmaxf(s[nt][0], s[nt][1]));
            mxB = fmaxf(mxB, fmaxf(s[nt][2], s[nt][3]));
        }
        mxA = fmaxf(mxA, __shfl_xor_sync(0xffffffffu, mxA, 1));
        mxA = fmaxf(mxA, __shfl_xor_sync(0xffffffffu, mxA, 2));
        mxB = fmaxf(mxB, __shfl_xor_sync(0xffffffffu, mxB, 1));
        mxB = fmaxf(mxB, __shfl_xor_sync(0xffffffffu, mxB, 2));

        float mAn = fmaxf(mA, mxA), mBn = fmaxf(mB, mxB);
        float cA = __expf(mA - mAn), cB = __expf(mB - mBn);
        float sumA = 0.0f, sumB = 0.0f;
#pragma unroll
        for (int nt = 0; nt < 4; nt++) {
            s[nt][0] = __expf(s[nt][0] - mAn);
            s[nt][1] = __expf(s[nt][1] - mAn);
            s[nt][2] = __expf(s[nt][2] - mBn);
            s[nt][3] = __expf(s[nt][3] - mBn);
            sumA += s[nt][0] + s[nt][1];
            sumB += s[nt][2] + s[nt][3];
        }
        sumA += __shfl_xor_sync(0xffffffffu, sumA, 1);
        sumA += __shfl_xor_sync(0xffffffffu, sumA, 2);
        sumB += __shfl_xor_sync(0xffffffffu, sumB, 1);
        sumB += __shfl_xor_sync(0xffffffffu, sumB, 2);
        lA = lA * cA + sumA;
        lB = lB * cB + sumB;
        mA = mAn; mB = mBn;
#pragma unroll
        for (int nt = 0; nt < 16; nt++) {
            acc[nt][0] *= cA; acc[nt][1] *= cA;
            acc[nt][2] *= cB; acc[nt][3] *= cB;
        }

        __syncthreads();
#pragma unroll
        for (int i = 0; i < 8; i++) {
            int f4 = tid + 128 * i;
            int row = f4 >> 5, c4 = f4 & 31;
            *(float4*)&KVs[row * 128 + ((c4 ^ (row & 7)) << 2)] =
                *(const float4*)&g_v[(base + kb + row) * H_ + c4 * 4];
        }
        __syncthreads();

        const int srcE = (lane & ~3) | (tig >> 1);
        const int srcO = srcE + 2;
        const int gh   = g >> 2;
        const int gl   = g & 3;
#pragma unroll
        for (int ka = 0; ka < 4; ka++) {
            float e, o, a0f, a1f, a2f, a3f;
            e = __shfl_sync(0xffffffffu, s[ka][0], srcE);
            o = __shfl_sync(0xffffffffu, s[ka][1], srcE);
            a0f = (tig & 1) ? o : e;
            e = __shfl_sync(0xffffffffu, s[ka][0], srcO);
            o = __shfl_sync(0xffffffffu, s[ka][1], srcO);
            a2f = (tig & 1) ? o : e;
            e = __shfl_sync(0xffffffffu, s[ka][2], srcE);
            o = __shfl_sync(0xffffffffu, s[ka][3], srcE);
            a1f = (tig & 1) ? o : e;
            e = __shfl_sync(0xffffffffu, s[ka][2], srcO);
            o = __shfl_sync(0xffffffffu, s[ka][3], srcO);
            a3f = (tig & 1) ? o : e;

            unsigned aH[4], aL[4];
            split_tf(a0f, aH[0], aL[0]);
            split_tf(a1f, aH[1], aL[1]);
            split_tf(a2f, aH[2], aL[2]);
            split_tf(a3f, aH[3], aL[3]);

            const float* v0 = &KVs[(8 * ka + tig) * 128 + gl];
            const float* v1 = &KVs[(8 * ka + tig + 4) * 128 + gl];
#pragma unroll
            for (int nt = 0; nt < 16; nt++) {
                const int o0 = ((2 * nt + gh) ^ tig) << 2;
                const int o1 = o0 ^ 16;
                unsigned bH[2], bL[2];
                split_tf(v0[o0], bH[0], bL[0]);
                split_tf(v1[o1], bH[1], bL[1]);
                MMA_TF32(acc[nt], aH, bH);
                MMA_TF32(acc[nt], aH, bL);
                MMA_TF32(acc[nt], aL, bH);
            }
        }
    }

    const size_t growA = (size_t)split * M_ + base + rowA;
    const size_t growB = growA + 8;
#pragma unroll
    for (int nt = 0; nt < 16; nt++) {
        *(float2*)&g_opart[growA * H_ + 8 * nt + 2 * tig] =
            make_float2(acc[nt][0], acc[nt][1]);
        *(float2*)&g_opart[growB * H_ + 8 * nt + 2 * tig] =
            make_float2(acc[nt][2], acc[nt][3]);
    }
    if (tig == 0) {
        g_mpart[growA] = mA; g_lpart[growA] = lA;
        g_mpart[growB] = mB; g_lpart[growB] = lB;
    }
}

// ---------------------------------------------------------------------------
// Combine kernel: merge NSPLIT partials per row.
// ---------------------------------------------------------------------------
__global__ __launch_bounds__(256) void combine_kernel(float* __restrict__ out)
{
    const int t   = blockIdx.x * 256 + threadIdx.x;
    const int row = t >> 5;
    const int h   = (t & 31) * 4;

    const int qt  = (row & (S_ - 1)) >> 6;            // QTB=64
    const int nkt = 2 * (qt + 1);
    const int ck  = (nkt + NSPLIT - 1) / NSPLIT;

    float ms[NSPLIT];
    float M = -1e30f;
#pragma unroll
    for (int sp = 0; sp < NSPLIT; sp++) {
        bool valid = (sp * ck < nkt);
        ms[sp] = valid ? g_mpart[sp * M_ + row] : -1e30f;
        M = fmaxf(M, ms[sp]);
    }

    float L = 0.0f;
    float4 o = make_float4(0.f, 0.f, 0.f, 0.f);
#pragma unroll
    for (int sp = 0; sp < NSPLIT; sp++) {
        if (sp * ck < nkt) {
            float e = __expf(ms[sp] - M);
            L += e * g_lpart[sp * M_ + row];
            float4 v = *(const float4*)&g_opart[((size_t)sp * M_ + row) * H_ + h];
            o.x += e * v.x; o.y += e * v.y; o.z += e * v.z; o.w += e * v.w;
        }
    }
    float inv = 1.0f / L;
    float4 rr = make_float4(o.x * inv, o.y * inv, o.z * inv, o.w * inv);
    *(float4*)&out[(size_t)row * H_ + h] = rr;
}

// ---------------------------------------------------------------------------
extern "C" void kernel_launch(void* const* d_in, const int* in_sizes, int n_in,
                              void* d_out, int out_size)
{
    const float* x  = (const float*)d_in[0];
    const float* Wq = (const float*)d_in[1];
    const float* Wk = (const float*)d_in[2];
    const float* Wv = (const float*)d_in[3];
    float* out = (float*)d_out;

    dim3 pg(M_ / 128, 3);
    proj_kernel<<<pg, 256>>>(x, Wq, Wk, Wv);
    attn_kernel<<<NSPLIT * B_ * NQT, 128>>>();
    combine_kernel<<<(M_ * H_ / 4) / 256, 256>>>(out);
}